// round 16
// baseline (speedup 1.0000x reference)
#include <cuda_runtime.h>
#include <cuda_fp16.h>
#include <math.h>
#include <stdint.h>

#define Bq 16
#define Sq 2048
#define Hq 1024
#define Dq 512
#define MSq (Bq * Sq)   // 32768

// ---------------- scratch (__device__ globals; no allocations) ----------------
__device__ __half g_hs[(size_t)MSq * Hq];
__device__ __half g_wqT[(size_t)Dq * Hq];
__device__ __half g_wkT[(size_t)Dq * Hq];
__device__ __half g_w1T[(size_t)Dq * Hq];
__device__ __half g_q[(size_t)MSq * Dq];
__device__ __half g_k[(size_t)MSq * Dq];
__device__ __half g_hw1[(size_t)MSq * Dq];           // fp16 [B*S, D]
__device__ __half g_hw1t[(size_t)Bq * Dq * Sq];      // [b][n][t]
__device__ __half g_scores[(size_t)Bq * Sq * Sq];    // fp16 scores (128 MB)
__device__ __half g_p[(size_t)Bq * Sq * Sq];
__device__ __half g_h[(size_t)MSq * Dq];             // fp16 h (probs @ hw1)
__device__ int    g_len[Bq];
__device__ float  g_ratlen[Bq];
__device__ int    g_spanstart[Bq];
__device__ int    g_spanlen[Bq];

// ---------------- helpers ----------------
__device__ __forceinline__ uint32_t smem_u32(const void* p) {
    uint32_t a;
    asm("{ .reg .u64 t; cvta.to.shared.u64 t, %1; cvt.u32.u64 %0, t; }" : "=r"(a) : "l"(p));
    return a;
}
__device__ __forceinline__ void cpa16(uint32_t s, const void* g) {
    asm volatile("cp.async.cg.shared.global [%0], [%1], 16;" :: "r"(s), "l"(g));
}
__device__ __forceinline__ void cpa_commit() {
    asm volatile("cp.async.commit_group;" ::: "memory");
}
template<int N> __device__ __forceinline__ void cpa_wait() {
    asm volatile("cp.async.wait_group %0;" :: "n"(N) : "memory");
}
__device__ __forceinline__ void ldm4(uint32_t* d, uint32_t a) {
    asm volatile("ldmatrix.sync.aligned.m8n8.x4.shared.b16 {%0,%1,%2,%3}, [%4];"
        : "=r"(d[0]), "=r"(d[1]), "=r"(d[2]), "=r"(d[3]) : "r"(a));
}
__device__ __forceinline__ void mma16816h(float* c, const uint32_t* a, const uint32_t* b) {
    asm volatile("mma.sync.aligned.m16n8k16.row.col.f32.f16.f16.f32 "
        "{%0,%1,%2,%3}, {%4,%5,%6,%7}, {%8,%9}, {%0,%1,%2,%3};"
        : "+f"(c[0]), "+f"(c[1]), "+f"(c[2]), "+f"(c[3])
        : "r"(a[0]), "r"(a[1]), "r"(a[2]), "r"(a[3]), "r"(b[0]), "r"(b[1]));
}
__device__ __forceinline__ uint32_t swz(int r, int chunk) {
    return ((uint32_t)r << 7) + (uint32_t)((chunk ^ (r & 7)) << 4);
}

// ---------------------------------------------------------------------------
// fp16 mma.sync GEMM (fp32 accum). CTA tile 128x64, warp tile 32x32 (8 warps,
// 4(M) x 2(N)), K-chunk 64, 3-stage cp.async (24KB/stage). 3 CTAs/SM target.
// MODE 0: fused projections. grid.x=24; rng = n0>>9 selects {q,k,hw1}.
// MODE 2: scores (half out, alpha; skip m0>=len || n0>=len)
// MODE 3: probs  (half out; skip m0>=len, clamp K to len)
// ---------------------------------------------------------------------------
#define MM_SMEM 73728   // 3 x (16KB A + 8KB B)

template<int MODE>
__global__ void __launch_bounds__(256, 3)
mma_gemm(const __half* __restrict__ A,
         const __half* __restrict__ B0, const __half* __restrict__ B1,
         const __half* __restrict__ B2,
         const float* __restrict__ bias0, const float* __restrict__ bias1,
         float alpha,
         __half* __restrict__ Ch0, __half* __restrict__ Ch1, __half* __restrict__ Ch2,
         int K, int ldc, long long sA, long long sB, long long sC)
{
    extern __shared__ char dsm[];
    const uint32_t sb0 = smem_u32(dsm);
    const int tid  = threadIdx.x;
    const int lane = tid & 31;
    const int wid  = tid >> 5;
    const int wm   = wid & 3;      // 4 M-positions of 32 rows
    const int wn   = wid >> 2;     // 2 N-positions of 32 cols

    const long long z = blockIdx.z;
    const int m0 = blockIdx.y * 128;
    const int n0 = blockIdx.x * 64;

    int NK = K >> 6;
    const __half* B;
    __half* Ch;
    const float* bias;
    int ncol;
    bool hasBias = false;
    if (MODE == 0) {
        if ((m0 & 2047) >= g_len[m0 >> 11]) return;
        const int rng = n0 >> 9;
        ncol = n0 & 511;
        B    = (rng == 0) ? B0 : (rng == 1) ? B1 : B2;
        Ch   = (rng == 0) ? Ch0 : (rng == 1) ? Ch1 : Ch2;
        bias = (rng == 0) ? bias0 : bias1;
        hasBias = (rng < 2);
    } else if (MODE == 2) {
        const int len = g_len[z];
        if (m0 >= len || n0 >= len) return;
        B = B0; Ch = Ch0; bias = nullptr; ncol = n0;
    } else {
        const int len = g_len[z];
        if (m0 >= len) return;
        const int nk2 = (len + 63) >> 6;
        if (nk2 < NK) NK = nk2;
        B = B0; Ch = Ch0; bias = nullptr; ncol = n0;
    }

    const __half* pA = A + z * sA;
    const __half* pB = B + z * sB;

    // A: 128 rows x 128B; 2 threads/row, 4 chunks each.
    const int ar_ld = tid >> 1;
    const int ac_ld = (tid & 1) << 2;
    // B: 64 rows x 128B; 4 threads/row, 2 chunks each.
    const int br_ld = tid >> 2;
    const int bc_ld = (tid & 3) << 1;
    const long long arow = (long long)(m0 + ar_ld) * K;
    const long long brow = (long long)(ncol + br_ld) * K;

    auto issue = [&](int kt) {
        const uint32_t so = sb0 + (uint32_t)(kt % 3) * 24576u;
        const int k0 = kt << 6;
#pragma unroll
        for (int i = 0; i < 4; i++) {
            const int ch = ac_ld + i;
            cpa16(so + swz(ar_ld, ch), pA + arow + k0 + ch * 8);
        }
#pragma unroll
        for (int i = 0; i < 2; i++) {
            const int ch = bc_ld + i;
            cpa16(so + 16384u + swz(br_ld, ch), pB + brow + k0 + ch * 8);
        }
        cpa_commit();
    };

    float acc[2][4][4];
#pragma unroll
    for (int i = 0; i < 2; i++)
#pragma unroll
        for (int j = 0; j < 4; j++)
#pragma unroll
            for (int e = 0; e < 4; e++) acc[i][j][e] = 0.f;

    const int l15 = lane & 15, lhi = lane >> 4;
    int rA[2], rB[2];
#pragma unroll
    for (int mi = 0; mi < 2; mi++) rA[mi] = wm * 32 + mi * 16 + l15;
#pragma unroll
    for (int bj = 0; bj < 2; bj++) rB[bj] = wn * 32 + bj * 16 + l15;

    issue(0);
    if (NK > 1) issue(1);

#pragma unroll 1
    for (int kt = 0; kt < NK; kt++) {
        if (kt + 2 < NK) { issue(kt + 2); cpa_wait<2>(); }
        else if (kt + 1 < NK) cpa_wait<1>();
        else cpa_wait<0>();
        __syncthreads();

        const uint32_t uA = sb0 + (uint32_t)(kt % 3) * 24576u;
        const uint32_t uB = uA + 16384u;

#pragma unroll
        for (int ks = 0; ks < 4; ks++) {
            const int ch = ks * 2 + lhi;
            uint32_t ah[2][4], bh[4][2];
#pragma unroll
            for (int mi = 0; mi < 2; mi++) ldm4(ah[mi], uA + swz(rA[mi], ch));
#pragma unroll
            for (int bj = 0; bj < 2; bj++) {
                uint32_t q[4];
                ldm4(q, uB + swz(rB[bj], ch));
                bh[bj*2][0] = q[0]; bh[bj*2+1][0] = q[1];
                bh[bj*2][1] = q[2]; bh[bj*2+1][1] = q[3];
            }
#pragma unroll
            for (int mi = 0; mi < 2; mi++)
#pragma unroll
                for (int nj = 0; nj < 4; nj++)
                    mma16816h(acc[mi][nj], ah[mi], bh[nj]);
        }
        __syncthreads();
    }

    // ---- epilogue (all modes write fp16) ----
    __half* pCh = Ch + z * sC;
    const int r4 = lane >> 2, c2 = (lane & 3) << 1;
#pragma unroll
    for (int mi = 0; mi < 2; mi++) {
        const long long gm = (long long)(m0 + wm * 32 + mi * 16 + r4);
#pragma unroll
        for (int nj = 0; nj < 4; nj++) {
            const int gn = ncol + wn * 32 + nj * 8 + c2;
            float v0 = alpha * acc[mi][nj][0];
            float v1 = alpha * acc[mi][nj][1];
            float v2 = alpha * acc[mi][nj][2];
            float v3 = alpha * acc[mi][nj][3];
            if (MODE == 0 && hasBias) {
                const float bx = bias[gn], by = bias[gn + 1];
                v0 += bx; v1 += by; v2 += bx; v3 += by;
            }
            const long long o0 = gm * ldc + gn;
            const long long o1 = (gm + 8) * ldc + gn;
            union { __half h[2]; uint32_t u; } ph;
            ph.h[0] = __float2half(v0); ph.h[1] = __float2half(v1);
            *(uint32_t*)&pCh[o0] = ph.u;
            ph.h[0] = __float2half(v2); ph.h[1] = __float2half(v3);
            *(uint32_t*)&pCh[o1] = ph.u;
        }
    }
}

// ---------------- conversions ----------------
__global__ void convert_hs_kernel(const float* __restrict__ hs) {
    const size_t i = ((size_t)blockIdx.x * 256 + threadIdx.x) * 8;
    const int row = (int)(i >> 10);
    if ((row & 2047) >= g_len[row >> 11]) return;
    float4 a = *(const float4*)(hs + i);
    float4 b = *(const float4*)(hs + i + 4);
    union { uint4 q; __half v[8]; } hi;
    hi.v[0] = __float2half(a.x); hi.v[1] = __float2half(a.y);
    hi.v[2] = __float2half(a.z); hi.v[3] = __float2half(a.w);
    hi.v[4] = __float2half(b.x); hi.v[5] = __float2half(b.y);
    hi.v[6] = __float2half(b.z); hi.v[7] = __float2half(b.w);
    *(uint4*)&g_hs[i] = hi.q;
}

__global__ void convert_wT3_kernel(const float* __restrict__ W0, const float* __restrict__ W1,
                                   const float* __restrict__ W2,
                                   __half* __restrict__ T0, __half* __restrict__ T1,
                                   __half* __restrict__ T2) {
    __shared__ float t[32][33];
    const int zz = blockIdx.z;
    const float* W = (zz == 0) ? W0 : (zz == 1) ? W1 : W2;
    __half*      T = (zz == 0) ? T0 : (zz == 1) ? T1 : T2;
    const int nx = blockIdx.x * 32, ky = blockIdx.y * 32;
    const int x = threadIdx.x, y = threadIdx.y;
#pragma unroll
    for (int i = 0; i < 32; i += 8)
        t[y + i][x] = W[(size_t)(ky + y + i) * Dq + nx + x];
    __syncthreads();
#pragma unroll
    for (int i = 0; i < 32; i += 8)
        T[(size_t)(nx + y + i) * Hq + ky + x] = __float2half(t[x][y + i]);
}

__global__ void transpose_hw1_kernel() {
    __shared__ __half t[32][40];
    const int b = blockIdx.z;
    const int nx = blockIdx.x * 32, sy = blockIdx.y * 32;
    const int nk64 = (g_len[b] + 63) & ~63;
    if (sy >= nk64) return;
    const int x = threadIdx.x, y = threadIdx.y;
#pragma unroll
    for (int i = 0; i < 32; i += 8)
        t[y + i][x] = g_hw1[(size_t)(b * Sq + sy + y + i) * Dq + nx + x];
    __syncthreads();
#pragma unroll
    for (int i = 0; i < 32; i += 8)
        g_hw1t[(size_t)(b * Dq + nx + y + i) * Sq + sy + x] = t[x][y + i];
}

// ---------------- non-GEMM kernels ----------------
__global__ void lens_kernel(const int* __restrict__ mask) {
    __shared__ int red[256];
    const int b = blockIdx.x, tid = threadIdx.x;
    int s = 0;
    for (int t = tid; t < Sq; t += 256) s += mask[b * Sq + t];
    red[tid] = s; __syncthreads();
    for (int w = 128; w > 0; w >>= 1) { if (tid < w) red[tid] += red[tid + w]; __syncthreads(); }
    if (tid == 0) g_len[b] = red[0];
}

__global__ void softmax_scores_kernel() {
    __shared__ float buf[Sq];
    __shared__ float red[256];
    const int row = blockIdx.x;
    const int len = g_len[row >> 11];
    if ((row & 2047) >= len) return;
    const int nk64 = (len + 63) & ~63;
    const __half* x = g_scores + (size_t)row * Sq;
    const int tid = threadIdx.x;

    float m = -1e30f;
    for (int t = tid; t < len; t += 256) { float v = __half2float(x[t]); buf[t] = v; m = fmaxf(m, v); }
    red[tid] = m; __syncthreads();
    for (int w = 128; w > 0; w >>= 1) { if (tid < w) red[tid] = fmaxf(red[tid], red[tid + w]); __syncthreads(); }
    m = red[0]; __syncthreads();

    float s = 0.f;
    for (int t = tid; t < len; t += 256) { float e = __expf(buf[t] - m); buf[t] = e; s += e; }
    red[tid] = s; __syncthreads();
    for (int w = 128; w > 0; w >>= 1) { if (tid < w) red[tid] += red[tid + w]; __syncthreads(); }
    const float Z = red[0];

    for (int t = tid; t < nk64; t += 256)
        g_p[(size_t)row * Sq + t] = __float2half((t < len) ? buf[t] / Z : 0.f);
}

// warp-per-row LayerNorm+ReLU+dot: 4 rows/block, shfl reductions, no barriers.
__global__ void ln_score_kernel(const float* __restrict__ b1,
                                const float* __restrict__ lng, const float* __restrict__ lnb,
                                const float* __restrict__ W2,  const float* __restrict__ b2,
                                float* __restrict__ ts_out)
{
    const int row  = blockIdx.x * 4 + (threadIdx.x >> 5);
    const int lane = threadIdx.x & 31;
    const int b = row >> 11, sIdx = row & (Sq - 1);
    if (sIdx >= g_len[b]) { if (lane == 0) ts_out[row] = -10000.f; return; }
    const __half* h = g_h + (size_t)row * Dq;

    float v[16];
    float s = 0.f;
#pragma unroll
    for (int i = 0; i < 16; i++) {
        const int d = lane + i * 32;
        v[i] = __half2float(h[d]) + b1[d];
        s += v[i];
    }
#pragma unroll
    for (int o = 16; o > 0; o >>= 1) s += __shfl_xor_sync(0xFFFFFFFFu, s, o);
    const float mu = s / (float)Dq;

    float q = 0.f;
#pragma unroll
    for (int i = 0; i < 16; i++) { const float d = v[i] - mu; q += d * d; }
#pragma unroll
    for (int o = 16; o > 0; o >>= 1) q += __shfl_xor_sync(0xFFFFFFFFu, q, o);
    const float rstd = rsqrtf(q / (float)Dq + 1e-5f);

    float acc = 0.f;
#pragma unroll
    for (int i = 0; i < 16; i++) {
        const int d = lane + i * 32;
        float y = (v[i] - mu) * rstd * lng[d] + lnb[d];
        y = fmaxf(y, 0.f);
        acc += y * W2[d];
    }
#pragma unroll
    for (int o = 16; o > 0; o >>= 1) acc += __shfl_xor_sync(0xFFFFFFFFu, acc, o);
    if (lane == 0) ts_out[row] = acc + b2[0];
}

// Span argmax (parallel cumsum) + rationale write + token_probs (merged).
__global__ void rationale_kernel(const float* __restrict__ ts_all,
                                 float* __restrict__ rat_out, float* __restrict__ tp_out)
{
    __shared__ float cum[Sq];
    __shared__ float part[256];
    __shared__ float rv[256];
    __shared__ int   ri[256];
    const int b = blockIdx.x, tid = threadIdx.x;
    const float* ts = ts_all + b * Sq;

    for (int t = tid; t < Sq; t += 256) cum[t] = ts[t];
    __syncthreads();

    float loc[8];
    {
        float s = 0.f;
#pragma unroll
        for (int i = 0; i < 8; i++) { s += cum[tid * 8 + i]; loc[i] = s; }
        part[tid] = s;
    }
    __syncthreads();
    for (int off = 1; off < 256; off <<= 1) {
        float add = (tid >= off) ? part[tid - off] : 0.f;
        __syncthreads();
        part[tid] += add;
        __syncthreads();
    }
    {
        const float base = (tid > 0) ? part[tid - 1] : 0.f;
#pragma unroll
        for (int i = 0; i < 8; i++) cum[tid * 8 + i] = loc[i] + base;
    }
    __syncthreads();

    const int vl = g_len[b];
    float best = -1e38f; int bi = 1 << 30;
    for (int idx = tid; idx < 18 * Sq; idx += 256) {
        const int Li = idx >> 11;
        const int s  = idx & (Sq - 1);
        const int L  = 3 + Li;
        if (L <= vl && s <= vl - L) {
            int e = s + L - 1; if (e > Sq - 1) e = Sq - 1;
            const float val = cum[e] / (float)L + 0.01f * ((float)L / 20.0f);
            if (val > best || (val == best && idx < bi)) { best = val; bi = idx; }
        }
    }
    rv[tid] = best; ri[tid] = bi; __syncthreads();
    for (int w = 128; w > 0; w >>= 1) {
        if (tid < w) {
            if (rv[tid + w] > rv[tid] || (rv[tid + w] == rv[tid] && ri[tid + w] < ri[tid])) {
                rv[tid] = rv[tid + w]; ri[tid] = ri[tid + w];
            }
        }
        __syncthreads();
    }
    int idx = ri[0];
    if (idx >= 18 * Sq) idx = 0;
    const int bestL = 3 + (idx >> 11);
    const int bests = idx & (Sq - 1);
    const bool shortc = (vl <= 3);

    for (int t = tid; t < Sq; t += 256) {
        const float r = shortc ? ((t < vl) ? 1.f : 0.f)
                               : ((t >= bests && t < bests + bestL) ? 1.f : 0.f);
        rat_out[b * Sq + t] = r;
    }
    if (tid == 0) {
        g_ratlen[b]    = shortc ? (float)vl : (float)bestL;
        g_spanstart[b] = shortc ? 0 : bests;
        g_spanlen[b]   = shortc ? vl : bestL;
    }

    __syncthreads();
    float m = -1e30f;
    for (int t = tid; t < Sq; t += 256) { float v = ts[t]; cum[t] = v; m = fmaxf(m, v); }
    rv[tid] = m; __syncthreads();
    for (int w = 128; w > 0; w >>= 1) { if (tid < w) rv[tid] = fmaxf(rv[tid], rv[tid + w]); __syncthreads(); }
    m = rv[0]; __syncthreads();

    float s = 0.f;
    for (int t = tid; t < Sq; t += 256) { float e = __expf(cum[t] - m); cum[t] = e; s += e; }
    rv[tid] = s; __syncthreads();
    for (int w = 128; w > 0; w >>= 1) { if (tid < w) rv[tid] += rv[tid + w]; __syncthreads(); }
    const float Z = rv[0];
    for (int t = tid; t < Sq; t += 256) tp_out[b * Sq + t] = cum[t] / Z;
}

// attended + pooled: grid (4 h-chunks, 4 s-chunks, 16 b). Span owner writes pooled.
__global__ void attended_pooled_kernel(const float* __restrict__ hs,
                                       float* __restrict__ att, float* __restrict__ pooled)
{
    const int b = blockIdx.z;
    const int h = blockIdx.x * 256 + threadIdx.x;
    const int s0 = blockIdx.y * 512, s1 = s0 + 512;
    const int ss = g_spanstart[b];
    const int se = ss + g_spanlen[b];

    const float* hsb = hs  + (size_t)b * Sq * Hq + h;
    float*      attb = att + (size_t)b * Sq * Hq + h;
    for (int s = s0; s < s1; s++) {
        const bool in = (s >= ss) & (s < se);
        attb[(size_t)s * Hq] = in ? hsb[(size_t)s * Hq] : 0.f;
    }
    if (ss >= s0 && ss < s1) {
        float acc = 0.f;
        for (int s = ss; s < se; s++) acc += hsb[(size_t)s * Hq];
        pooled[b * Hq + h] = acc / (g_ratlen[b] + 1e-6f);
    }
}

// ---------------------------------------------------------------------------
extern "C" void kernel_launch(void* const* d_in, const int* in_sizes, int n_in,
                              void* d_out, int out_size)
{
    (void)in_sizes; (void)n_in; (void)out_size;
    const float* hs  = (const float*)d_in[0];
    const int*   am  = (const int*)  d_in[1];
    const float* Wq  = (const float*)d_in[2];
    const float* bq  = (const float*)d_in[3];
    const float* Wk  = (const float*)d_in[4];
    const float* bk  = (const float*)d_in[5];
    const float* W1  = (const float*)d_in[6];
    const float* b1  = (const float*)d_in[7];
    const float* lng = (const float*)d_in[8];
    const float* lnb = (const float*)d_in[9];
    const float* W2  = (const float*)d_in[10];
    const float* b2  = (const float*)d_in[11];

    float* out    = (float*)d_out;
    float* ts     = out;
    float* rat    = out + (size_t)MSq;
    float* tp     = out + (size_t)2 * MSq;
    float* att    = out + (size_t)3 * MSq;
    float* pooled = out + (size_t)3 * MSq + (size_t)MSq * Hq;

    __half *phs, *pwq, *pwk, *pw1, *pq, *pk, *phw1, *ph1t, *pp, *psc, *phb;
    cudaGetSymbolAddress((void**)&phs, g_hs);
    cudaGetSymbolAddress((void**)&pwq, g_wqT);
    cudaGetSymbolAddress((void**)&pwk, g_wkT);
    cudaGetSymbolAddress((void**)&pw1, g_w1T);
    cudaGetSymbolAddress((void**)&pq,  g_q);
    cudaGetSymbolAddress((void**)&pk,  g_k);
    cudaGetSymbolAddress((void**)&phw1, g_hw1);
    cudaGetSymbolAddress((void**)&ph1t, g_hw1t);
    cudaGetSymbolAddress((void**)&pp,  g_p);
    cudaGetSymbolAddress((void**)&psc, g_scores);
    cudaGetSymbolAddress((void**)&phb, g_h);

    cudaFuncSetAttribute(mma_gemm<0>, cudaFuncAttributeMaxDynamicSharedMemorySize, MM_SMEM);
    cudaFuncSetAttribute(mma_gemm<2>, cudaFuncAttributeMaxDynamicSharedMemorySize, MM_SMEM);
    cudaFuncSetAttribute(mma_gemm<3>, cudaFuncAttributeMaxDynamicSharedMemorySize, MM_SMEM);

    lens_kernel<<<Bq, 256>>>(am);
    convert_wT3_kernel<<<dim3(Dq / 32, Hq / 32, 3), dim3(32, 8)>>>(Wq, Wk, W1, pwq, pwk, pw1);
    convert_hs_kernel<<<(int)(((size_t)MSq * Hq) / 8 / 256), 256>>>(hs);

    // fused projections: M=32768, N=3x512, K=1024; hs read once
    dim3 gP(24, MSq / 128, 1);
    mma_gemm<0><<<gP, 256, MM_SMEM>>>(phs, pwq, pwk, pw1, bq, bk, 1.f,
        pq, pk, phw1, Hq, Dq, 0, 0, 0);

    // scores = Q @ K^T / sqrt(D) -> fp16 (skip dead blocks)
    dim3 gS(Sq / 64, Sq / 128, Bq);
    mma_gemm<2><<<gS, 256, MM_SMEM>>>(pq, pk, nullptr, nullptr, nullptr, nullptr,
        0.044194173824159216f, psc, nullptr, nullptr, Dq, Sq,
        (long long)Sq * Dq, (long long)Sq * Dq, (long long)Sq * Sq);

    transpose_hw1_kernel<<<dim3(Dq / 32, Sq / 32, Bq), dim3(32, 8)>>>();
    softmax_scores_kernel<<<MSq, 256>>>();

    // h = probs @ HSW1 -> fp16: per batch 2048x512, K clamped to len
    dim3 gH(Dq / 64, Sq / 128, Bq);
    mma_gemm<3><<<gH, 256, MM_SMEM>>>(pp, ph1t, nullptr, nullptr, nullptr, nullptr, 1.f,
        phb, nullptr, nullptr, Sq, Dq,
        (long long)Sq * Sq, (long long)Dq * Sq, (long long)Sq * Dq);

    ln_score_kernel<<<MSq / 4, 128>>>(b1, lng, lnb, W2, b2, ts);
    rationale_kernel<<<Bq, 256>>>(ts, rat, tp);
    attended_pooled_kernel<<<dim3(Hq / 256, 4, Bq), 256>>>(hs, att, pooled);
}

// round 17
// speedup vs baseline: 1.5206x; 1.5206x over previous
#include <cuda_runtime.h>
#include <cuda_fp16.h>
#include <math.h>
#include <stdint.h>

#define Bq 16
#define Sq 2048
#define Hq 1024
#define Dq 512
#define MSq (Bq * Sq)   // 32768

// ---------------- scratch (__device__ globals; no allocations) ----------------
__device__ __half g_hs[(size_t)MSq * Hq];
__device__ __half g_wqT[(size_t)Dq * Hq];
__device__ __half g_wkT[(size_t)Dq * Hq];
__device__ __half g_w1T[(size_t)Dq * Hq];
__device__ __half g_q[(size_t)MSq * Dq];
__device__ __half g_k[(size_t)MSq * Dq];
__device__ __half g_hw1[(size_t)MSq * Dq];           // fp16 [B*S, D]
__device__ __half g_hw1t[(size_t)Bq * Dq * Sq];      // [b][n][t]
__device__ __half g_scores[(size_t)Bq * Sq * Sq];    // fp16 scores (128 MB)
__device__ __half g_p[(size_t)Bq * Sq * Sq];
__device__ __half g_h[(size_t)MSq * Dq];             // fp16 h (probs @ hw1)
__device__ int    g_len[Bq];
__device__ float  g_ratlen[Bq];
__device__ int    g_spanstart[Bq];
__device__ int    g_spanlen[Bq];

// ---------------- helpers ----------------
__device__ __forceinline__ uint32_t smem_u32(const void* p) {
    uint32_t a;
    asm("{ .reg .u64 t; cvta.to.shared.u64 t, %1; cvt.u32.u64 %0, t; }" : "=r"(a) : "l"(p));
    return a;
}
__device__ __forceinline__ void cpa16(uint32_t s, const void* g) {
    asm volatile("cp.async.cg.shared.global [%0], [%1], 16;" :: "r"(s), "l"(g));
}
__device__ __forceinline__ void cpa_commit() {
    asm volatile("cp.async.commit_group;" ::: "memory");
}
template<int N> __device__ __forceinline__ void cpa_wait() {
    asm volatile("cp.async.wait_group %0;" :: "n"(N) : "memory");
}
__device__ __forceinline__ void ldm4(uint32_t* d, uint32_t a) {
    asm volatile("ldmatrix.sync.aligned.m8n8.x4.shared.b16 {%0,%1,%2,%3}, [%4];"
        : "=r"(d[0]), "=r"(d[1]), "=r"(d[2]), "=r"(d[3]) : "r"(a));
}
__device__ __forceinline__ void mma16816h(float* c, const uint32_t* a, const uint32_t* b) {
    asm volatile("mma.sync.aligned.m16n8k16.row.col.f32.f16.f16.f32 "
        "{%0,%1,%2,%3}, {%4,%5,%6,%7}, {%8,%9}, {%0,%1,%2,%3};"
        : "+f"(c[0]), "+f"(c[1]), "+f"(c[2]), "+f"(c[3])
        : "r"(a[0]), "r"(a[1]), "r"(a[2]), "r"(a[3]), "r"(b[0]), "r"(b[1]));
}
__device__ __forceinline__ uint32_t swz(int r, int chunk) {
    return ((uint32_t)r << 7) + (uint32_t)((chunk ^ (r & 7)) << 4);
}

// ---------------------------------------------------------------------------
// R14 engine (measured best: proj 328us): fp16 mma.sync, 128x128 tile,
// K-chunk 64, 3-stage cp.async + B-fragment double-buffer.
// MODE 0: fused projections. grid.x=12; rng = n0>>9 selects {q,k,hw1}.
// MODE 2: scores (half out, alpha; skip m0>=len || n0>=len)
// MODE 3: probs  (half out; skip m0>=len, clamp K to len)
// ---------------------------------------------------------------------------
#define MM_SMEM 98304

template<int MODE>
__global__ void __launch_bounds__(256)
mma_gemm(const __half* __restrict__ A,
         const __half* __restrict__ B0, const __half* __restrict__ B1,
         const __half* __restrict__ B2,
         const float* __restrict__ bias0, const float* __restrict__ bias1,
         float alpha,
         __half* __restrict__ Ch0, __half* __restrict__ Ch1, __half* __restrict__ Ch2,
         int K, int ldc, long long sA, long long sB, long long sC)
{
    extern __shared__ char dsm[];
    const uint32_t sb0 = smem_u32(dsm);
    const int tid  = threadIdx.x;
    const int lane = tid & 31;
    const int wid  = tid >> 5;
    const int wm   = wid & 1;
    const int wn   = wid >> 1;

    const long long z = blockIdx.z;
    const int m0 = blockIdx.y * 128;
    const int n0 = blockIdx.x * 128;

    int NK = K >> 6;
    const __half* B;
    __half* Ch;
    const float* bias;
    int ncol;
    bool hasBias = false;
    if (MODE == 0) {
        if ((m0 & 2047) >= g_len[m0 >> 11]) return;
        const int rng = n0 >> 9;
        ncol = n0 & 511;
        B    = (rng == 0) ? B0 : (rng == 1) ? B1 : B2;
        Ch   = (rng == 0) ? Ch0 : (rng == 1) ? Ch1 : Ch2;
        bias = (rng == 0) ? bias0 : bias1;
        hasBias = (rng < 2);
    } else if (MODE == 2) {
        const int len = g_len[z];
        if (m0 >= len || n0 >= len) return;
        B = B0; Ch = Ch0; bias = nullptr; ncol = n0;
    } else {
        const int len = g_len[z];
        if (m0 >= len) return;
        const int nk2 = (len + 63) >> 6;
        if (nk2 < NK) NK = nk2;
        B = B0; Ch = Ch0; bias = nullptr; ncol = n0;
    }

    const __half* pA = A + z * sA;
    const __half* pB = B + z * sB;

    const int r_ld  = tid >> 1;
    const int cu_ld = (tid & 1) << 2;
    const long long arow = (long long)(m0 + r_ld) * K;
    const long long brow = (long long)(ncol + r_ld) * K;

    auto issue = [&](int kt) {
        const uint32_t so = sb0 + (uint32_t)(kt % 3) * 32768u;
        const int k0 = kt << 6;
#pragma unroll
        for (int i = 0; i < 4; i++) {
            const int ch = cu_ld + i;
            const uint32_t sw = swz(r_ld, ch);
            const int go = k0 + ch * 8;
            cpa16(so +     0 + sw, pA + arow + go);
            cpa16(so + 16384 + sw, pB + brow + go);
        }
        cpa_commit();
    };

    float acc[4][4][4];
#pragma unroll
    for (int i = 0; i < 4; i++)
#pragma unroll
        for (int j = 0; j < 4; j++)
#pragma unroll
            for (int e = 0; e < 4; e++) acc[i][j][e] = 0.f;

    const int l15 = lane & 15, lhi = lane >> 4;
    int rA[4], rB[2];
#pragma unroll
    for (int mi = 0; mi < 4; mi++) rA[mi] = wm * 64 + mi * 16 + l15;
#pragma unroll
    for (int bj = 0; bj < 2; bj++) rB[bj] = wn * 32 + bj * 16 + l15;

    issue(0);
    if (NK > 1) issue(1);

#pragma unroll 1
    for (int kt = 0; kt < NK; kt++) {
        if (kt + 2 < NK) { issue(kt + 2); cpa_wait<2>(); }
        else if (kt + 1 < NK) cpa_wait<1>();
        else cpa_wait<0>();
        __syncthreads();

        const uint32_t uA = sb0 + (uint32_t)(kt % 3) * 32768u;
        const uint32_t uB = uA + 16384;

        uint32_t bfr[2][4][2];
        {
#pragma unroll
            for (int bj = 0; bj < 2; bj++) {
                uint32_t q[4];
                ldm4(q, uB + swz(rB[bj], lhi));
                bfr[0][bj*2][0] = q[0]; bfr[0][bj*2+1][0] = q[1];
                bfr[0][bj*2][1] = q[2]; bfr[0][bj*2+1][1] = q[3];
            }
        }
#pragma unroll
        for (int ks = 0; ks < 4; ks++) {
            const int ch = ks * 2 + lhi;
            uint32_t ah[4][4];
#pragma unroll
            for (int mi = 0; mi < 4; mi++) ldm4(ah[mi], uA + swz(rA[mi], ch));
            if (ks < 3) {
                const int chn = (ks + 1) * 2 + lhi;
                const int nb = (ks + 1) & 1;
#pragma unroll
                for (int bj = 0; bj < 2; bj++) {
                    uint32_t q[4];
                    ldm4(q, uB + swz(rB[bj], chn));
                    bfr[nb][bj*2][0] = q[0]; bfr[nb][bj*2+1][0] = q[1];
                    bfr[nb][bj*2][1] = q[2]; bfr[nb][bj*2+1][1] = q[3];
                }
            }
            const int cb = ks & 1;
#pragma unroll
            for (int mi = 0; mi < 4; mi++)
#pragma unroll
                for (int nj = 0; nj < 4; nj++)
                    mma16816h(acc[mi][nj], ah[mi], bfr[cb][nj]);
        }
        __syncthreads();
    }

    // ---- epilogue (all modes write fp16) ----
    __half* pCh = Ch + z * sC;
    const int r4 = lane >> 2, c2 = (lane & 3) << 1;
#pragma unroll
    for (int mi = 0; mi < 4; mi++) {
        const long long gm = (long long)(m0 + wm * 64 + mi * 16 + r4);
#pragma unroll
        for (int nj = 0; nj < 4; nj++) {
            const int gn = ncol + wn * 32 + nj * 8 + c2;
            float v0 = alpha * acc[mi][nj][0];
            float v1 = alpha * acc[mi][nj][1];
            float v2 = alpha * acc[mi][nj][2];
            float v3 = alpha * acc[mi][nj][3];
            if (MODE == 0 && hasBias) {
                const float bx = bias[gn], by = bias[gn + 1];
                v0 += bx; v1 += by; v2 += bx; v3 += by;
            }
            const long long o0 = gm * ldc + gn;
            const long long o1 = (gm + 8) * ldc + gn;
            union { __half h[2]; uint32_t u; } ph;
            ph.h[0] = __float2half(v0); ph.h[1] = __float2half(v1);
            *(uint32_t*)&pCh[o0] = ph.u;
            ph.h[0] = __float2half(v2); ph.h[1] = __float2half(v3);
            *(uint32_t*)&pCh[o1] = ph.u;
        }
    }
}

// ---------------- conversions ----------------
__global__ void convert_hs_kernel(const float* __restrict__ hs) {
    const size_t i = ((size_t)blockIdx.x * 256 + threadIdx.x) * 8;
    const int row = (int)(i >> 10);
    if ((row & 2047) >= g_len[row >> 11]) return;
    float4 a = *(const float4*)(hs + i);
    float4 b = *(const float4*)(hs + i + 4);
    union { uint4 q; __half v[8]; } hi;
    hi.v[0] = __float2half(a.x); hi.v[1] = __float2half(a.y);
    hi.v[2] = __float2half(a.z); hi.v[3] = __float2half(a.w);
    hi.v[4] = __float2half(b.x); hi.v[5] = __float2half(b.y);
    hi.v[6] = __float2half(b.z); hi.v[7] = __float2half(b.w);
    *(uint4*)&g_hs[i] = hi.q;
}

__global__ void convert_wT3_kernel(const float* __restrict__ W0, const float* __restrict__ W1,
                                   const float* __restrict__ W2,
                                   __half* __restrict__ T0, __half* __restrict__ T1,
                                   __half* __restrict__ T2) {
    __shared__ float t[32][33];
    const int zz = blockIdx.z;
    const float* W = (zz == 0) ? W0 : (zz == 1) ? W1 : W2;
    __half*      T = (zz == 0) ? T0 : (zz == 1) ? T1 : T2;
    const int nx = blockIdx.x * 32, ky = blockIdx.y * 32;
    const int x = threadIdx.x, y = threadIdx.y;
#pragma unroll
    for (int i = 0; i < 32; i += 8)
        t[y + i][x] = W[(size_t)(ky + y + i) * Dq + nx + x];
    __syncthreads();
#pragma unroll
    for (int i = 0; i < 32; i += 8)
        T[(size_t)(nx + y + i) * Hq + ky + x] = __float2half(t[x][y + i]);
}

__global__ void transpose_hw1_kernel() {
    __shared__ __half t[32][40];
    const int b = blockIdx.z;
    const int nx = blockIdx.x * 32, sy = blockIdx.y * 32;
    const int nk64 = (g_len[b] + 63) & ~63;
    if (sy >= nk64) return;
    const int x = threadIdx.x, y = threadIdx.y;
#pragma unroll
    for (int i = 0; i < 32; i += 8)
        t[y + i][x] = g_hw1[(size_t)(b * Sq + sy + y + i) * Dq + nx + x];
    __syncthreads();
#pragma unroll
    for (int i = 0; i < 32; i += 8)
        g_hw1t[(size_t)(b * Dq + nx + y + i) * Sq + sy + x] = t[x][y + i];
}

// ---------------- non-GEMM kernels ----------------
__global__ void lens_kernel(const int* __restrict__ mask) {
    __shared__ int red[256];
    const int b = blockIdx.x, tid = threadIdx.x;
    int s = 0;
    for (int t = tid; t < Sq; t += 256) s += mask[b * Sq + t];
    red[tid] = s; __syncthreads();
    for (int w = 128; w > 0; w >>= 1) { if (tid < w) red[tid] += red[tid + w]; __syncthreads(); }
    if (tid == 0) g_len[b] = red[0];
}

// half2-vectorized softmax (same float math; vector loads/stores)
__global__ void softmax_scores_kernel() {
    __shared__ float buf[Sq];
    __shared__ float red[256];
    const int row = blockIdx.x;
    const int len = g_len[row >> 11];
    if ((row & 2047) >= len) return;
    const int nk64 = (len + 63) & ~63;
    const __half2* x2 = (const __half2*)(g_scores + (size_t)row * Sq);
    const int tid = threadIdx.x;
    const int lenh = len >> 1;

    float m = -1e30f;
    for (int t = tid; t < lenh; t += 256) {
        const float2 v = __half22float2(x2[t]);
        buf[2*t] = v.x; buf[2*t+1] = v.y;
        m = fmaxf(m, fmaxf(v.x, v.y));
    }
    if ((len & 1) && tid == 0) {
        const float v = __half2float(((const __half*)x2)[len - 1]);
        buf[len - 1] = v; m = fmaxf(m, v);
    }
    red[tid] = m; __syncthreads();
    for (int w = 128; w > 0; w >>= 1) { if (tid < w) red[tid] = fmaxf(red[tid], red[tid + w]); __syncthreads(); }
    m = red[0]; __syncthreads();

    float s = 0.f;
    for (int t = tid; t < len; t += 256) { float e = __expf(buf[t] - m); buf[t] = e; s += e; }
    red[tid] = s; __syncthreads();
    for (int w = 128; w > 0; w >>= 1) { if (tid < w) red[tid] += red[tid + w]; __syncthreads(); }
    const float Z = red[0];

    __half2* p2 = (__half2*)(g_p + (size_t)row * Sq);
    const int nk64h = nk64 >> 1;
    for (int t = tid; t < nk64h; t += 256) {
        const int i0 = 2 * t, i1 = 2 * t + 1;
        const float a = (i0 < len) ? buf[i0] / Z : 0.f;
        const float b = (i1 < len) ? buf[i1] / Z : 0.f;
        p2[t] = __floats2half2_rn(a, b);
    }
}

// warp-per-row LayerNorm+ReLU+dot: 4 rows/block, shfl reductions, no barriers.
__global__ void ln_score_kernel(const float* __restrict__ b1,
                                const float* __restrict__ lng, const float* __restrict__ lnb,
                                const float* __restrict__ W2,  const float* __restrict__ b2,
                                float* __restrict__ ts_out)
{
    const int row  = blockIdx.x * 4 + (threadIdx.x >> 5);
    const int lane = threadIdx.x & 31;
    const int b = row >> 11, sIdx = row & (Sq - 1);
    if (sIdx >= g_len[b]) { if (lane == 0) ts_out[row] = -10000.f; return; }
    const __half* h = g_h + (size_t)row * Dq;

    float v[16];
    float s = 0.f;
#pragma unroll
    for (int i = 0; i < 16; i++) {
        const int d = lane + i * 32;
        v[i] = __half2float(h[d]) + b1[d];
        s += v[i];
    }
#pragma unroll
    for (int o = 16; o > 0; o >>= 1) s += __shfl_xor_sync(0xFFFFFFFFu, s, o);
    const float mu = s / (float)Dq;

    float q = 0.f;
#pragma unroll
    for (int i = 0; i < 16; i++) { const float d = v[i] - mu; q += d * d; }
#pragma unroll
    for (int o = 16; o > 0; o >>= 1) q += __shfl_xor_sync(0xFFFFFFFFu, q, o);
    const float rstd = rsqrtf(q / (float)Dq + 1e-5f);

    float acc = 0.f;
#pragma unroll
    for (int i = 0; i < 16; i++) {
        const int d = lane + i * 32;
        float y = (v[i] - mu) * rstd * lng[d] + lnb[d];
        y = fmaxf(y, 0.f);
        acc += y * W2[d];
    }
#pragma unroll
    for (int o = 16; o > 0; o >>= 1) acc += __shfl_xor_sync(0xFFFFFFFFu, acc, o);
    if (lane == 0) ts_out[row] = acc + b2[0];
}

// Span argmax (parallel cumsum) + rationale write + token_probs (merged).
__global__ void rationale_kernel(const float* __restrict__ ts_all,
                                 float* __restrict__ rat_out, float* __restrict__ tp_out)
{
    __shared__ float cum[Sq];
    __shared__ float part[256];
    __shared__ float rv[256];
    __shared__ int   ri[256];
    const int b = blockIdx.x, tid = threadIdx.x;
    const float* ts = ts_all + b * Sq;

    for (int t = tid; t < Sq; t += 256) cum[t] = ts[t];
    __syncthreads();

    float loc[8];
    {
        float s = 0.f;
#pragma unroll
        for (int i = 0; i < 8; i++) { s += cum[tid * 8 + i]; loc[i] = s; }
        part[tid] = s;
    }
    __syncthreads();
    for (int off = 1; off < 256; off <<= 1) {
        float add = (tid >= off) ? part[tid - off] : 0.f;
        __syncthreads();
        part[tid] += add;
        __syncthreads();
    }
    {
        const float base = (tid > 0) ? part[tid - 1] : 0.f;
#pragma unroll
        for (int i = 0; i < 8; i++) cum[tid * 8 + i] = loc[i] + base;
    }
    __syncthreads();

    const int vl = g_len[b];
    float best = -1e38f; int bi = 1 << 30;
    for (int idx = tid; idx < 18 * Sq; idx += 256) {
        const int Li = idx >> 11;
        const int s  = idx & (Sq - 1);
        const int L  = 3 + Li;
        if (L <= vl && s <= vl - L) {
            int e = s + L - 1; if (e > Sq - 1) e = Sq - 1;
            const float val = cum[e] / (float)L + 0.01f * ((float)L / 20.0f);
            if (val > best || (val == best && idx < bi)) { best = val; bi = idx; }
        }
    }
    rv[tid] = best; ri[tid] = bi; __syncthreads();
    for (int w = 128; w > 0; w >>= 1) {
        if (tid < w) {
            if (rv[tid + w] > rv[tid] || (rv[tid + w] == rv[tid] && ri[tid + w] < ri[tid])) {
                rv[tid] = rv[tid + w]; ri[tid] = ri[tid + w];
            }
        }
        __syncthreads();
    }
    int idx = ri[0];
    if (idx >= 18 * Sq) idx = 0;
    const int bestL = 3 + (idx >> 11);
    const int bests = idx & (Sq - 1);
    const bool shortc = (vl <= 3);

    for (int t = tid; t < Sq; t += 256) {
        const float r = shortc ? ((t < vl) ? 1.f : 0.f)
                               : ((t >= bests && t < bests + bestL) ? 1.f : 0.f);
        rat_out[b * Sq + t] = r;
    }
    if (tid == 0) {
        g_ratlen[b]    = shortc ? (float)vl : (float)bestL;
        g_spanstart[b] = shortc ? 0 : bests;
        g_spanlen[b]   = shortc ? vl : bestL;
    }

    __syncthreads();
    float m = -1e30f;
    for (int t = tid; t < Sq; t += 256) { float v = ts[t]; cum[t] = v; m = fmaxf(m, v); }
    rv[tid] = m; __syncthreads();
    for (int w = 128; w > 0; w >>= 1) { if (tid < w) rv[tid] = fmaxf(rv[tid], rv[tid + w]); __syncthreads(); }
    m = rv[0]; __syncthreads();

    float s = 0.f;
    for (int t = tid; t < Sq; t += 256) { float e = __expf(cum[t] - m); cum[t] = e; s += e; }
    rv[tid] = s; __syncthreads();
    for (int w = 128; w > 0; w >>= 1) { if (tid < w) rv[tid] += rv[tid + w]; __syncthreads(); }
    const float Z = rv[0];
    for (int t = tid; t < Sq; t += 256) tp_out[b * Sq + t] = cum[t] / Z;
}

// attended + pooled: grid (4 h-chunks, 4 s-chunks, 16 b). Span owner writes pooled.
__global__ void attended_pooled_kernel(const float* __restrict__ hs,
                                       float* __restrict__ att, float* __restrict__ pooled)
{
    const int b = blockIdx.z;
    const int h = blockIdx.x * 256 + threadIdx.x;
    const int s0 = blockIdx.y * 512, s1 = s0 + 512;
    const int ss = g_spanstart[b];
    const int se = ss + g_spanlen[b];

    const float* hsb = hs  + (size_t)b * Sq * Hq + h;
    float*      attb = att + (size_t)b * Sq * Hq + h;
    for (int s = s0; s < s1; s++) {
        const bool in = (s >= ss) & (s < se);
        attb[(size_t)s * Hq] = in ? hsb[(size_t)s * Hq] : 0.f;
    }
    if (ss >= s0 && ss < s1) {
        float acc = 0.f;
        for (int s = ss; s < se; s++) acc += hsb[(size_t)s * Hq];
        pooled[b * Hq + h] = acc / (g_ratlen[b] + 1e-6f);
    }
}

// ---------------------------------------------------------------------------
extern "C" void kernel_launch(void* const* d_in, const int* in_sizes, int n_in,
                              void* d_out, int out_size)
{
    (void)in_sizes; (void)n_in; (void)out_size;
    const float* hs  = (const float*)d_in[0];
    const int*   am  = (const int*)  d_in[1];
    const float* Wq  = (const float*)d_in[2];
    const float* bq  = (const float*)d_in[3];
    const float* Wk  = (const float*)d_in[4];
    const float* bk  = (const float*)d_in[5];
    const float* W1  = (const float*)d_in[6];
    const float* b1  = (const float*)d_in[7];
    const float* lng = (const float*)d_in[8];
    const float* lnb = (const float*)d_in[9];
    const float* W2  = (const float*)d_in[10];
    const float* b2  = (const float*)d_in[11];

    float* out    = (float*)d_out;
    float* ts     = out;
    float* rat    = out + (size_t)MSq;
    float* tp     = out + (size_t)2 * MSq;
    float* att    = out + (size_t)3 * MSq;
    float* pooled = out + (size_t)3 * MSq + (size_t)MSq * Hq;

    __half *phs, *pwq, *pwk, *pw1, *pq, *pk, *phw1, *ph1t, *pp, *psc, *phb;
    cudaGetSymbolAddress((void**)&phs, g_hs);
    cudaGetSymbolAddress((void**)&pwq, g_wqT);
    cudaGetSymbolAddress((void**)&pwk, g_wkT);
    cudaGetSymbolAddress((void**)&pw1, g_w1T);
    cudaGetSymbolAddress((void**)&pq,  g_q);
    cudaGetSymbolAddress((void**)&pk,  g_k);
    cudaGetSymbolAddress((void**)&phw1, g_hw1);
    cudaGetSymbolAddress((void**)&ph1t, g_hw1t);
    cudaGetSymbolAddress((void**)&pp,  g_p);
    cudaGetSymbolAddress((void**)&psc, g_scores);
    cudaGetSymbolAddress((void**)&phb, g_h);

    cudaFuncSetAttribute(mma_gemm<0>, cudaFuncAttributeMaxDynamicSharedMemorySize, MM_SMEM);
    cudaFuncSetAttribute(mma_gemm<2>, cudaFuncAttributeMaxDynamicSharedMemorySize, MM_SMEM);
    cudaFuncSetAttribute(mma_gemm<3>, cudaFuncAttributeMaxDynamicSharedMemorySize, MM_SMEM);

    lens_kernel<<<Bq, 256>>>(am);
    convert_wT3_kernel<<<dim3(Dq / 32, Hq / 32, 3), dim3(32, 8)>>>(Wq, Wk, W1, pwq, pwk, pw1);
    convert_hs_kernel<<<(int)(((size_t)MSq * Hq) / 8 / 256), 256>>>(hs);

    // fused projections: M=32768, N=3x512, K=1024; hs read once
    dim3 gP(12, MSq / 128, 1);
    mma_gemm<0><<<gP, 256, MM_SMEM>>>(phs, pwq, pwk, pw1, bq, bk, 1.f,
        pq, pk, phw1, Hq, Dq, 0, 0, 0);

    // scores = Q @ K^T / sqrt(D) -> fp16 (skip dead blocks)
    dim3 gS(Sq / 128, Sq / 128, Bq);
    mma_gemm<2><<<gS, 256, MM_SMEM>>>(pq, pk, nullptr, nullptr, nullptr, nullptr,
        0.044194173824159216f, psc, nullptr, nullptr, Dq, Sq,
        (long long)Sq * Dq, (long long)Sq * Dq, (long long)Sq * Sq);

    transpose_hw1_kernel<<<dim3(Dq / 32, Sq / 32, Bq), dim3(32, 8)>>>();
    softmax_scores_kernel<<<MSq, 256>>>();

    // h = probs @ HSW1 -> fp16: per batch 2048x512, K clamped to len
    dim3 gH(Dq / 128, Sq / 128, Bq);
    mma_gemm<3><<<gH, 256, MM_SMEM>>>(pp, ph1t, nullptr, nullptr, nullptr, nullptr, 1.f,
        phb, nullptr, nullptr, Sq, Dq,
        (long long)Sq * Sq, (long long)Dq * Sq, (long long)Sq * Dq);

    ln_score_kernel<<<MSq / 4, 128>>>(b1, lng, lnb, W2, b2, ts);
    rationale_kernel<<<Bq, 256>>>(ts, rat, tp);
    attended_pooled_kernel<<<dim3(Hq / 256, 4, Bq), 256>>>(hs, att, pooled);
}